// round 1
// baseline (speedup 1.0000x reference)
#include <cuda_runtime.h>
#include <math.h>

#define HW     (512*512)
#define NB     4
#define NC     64
#define HID    128
#define NK     16
#define SOFTEN 10000.0f
#define EPSV   1e-8f

// out layout: transformed_img [4,3,512,512] | m [4,16,512,512] | palette [4,16,3,1,1]
#define OFF_T  ((size_t)0)
#define OFF_M  ((size_t)NB * 3 * HW)
#define OFF_P  (OFF_M + (size_t)NB * NK * HW)

// scratch (no allocations allowed)
__device__ float         gNum[NB * NK * 3];
__device__ float         gDen[NB * NK];
__device__ float         gPal[NB * NK * 3];
__device__ unsigned char gArg[NB * HW];

__global__ void zero_kernel() {
    int t = threadIdx.x;
    if (t < NB * NK * 3) gNum[t] = 0.0f;
    if (t < NB * NK)     gDen[t] = 0.0f;
}

__global__ __launch_bounds__(256) void main_kernel(
    const float* __restrict__ img,
    const float* __restrict__ feat,
    const float* __restrict__ W1,
    const float* __restrict__ b1,
    const float* __restrict__ W2,
    float* __restrict__ out)
{
    __shared__ float W1s[HID * NC];   // [o][c], c contiguous
    __shared__ float W2s[HID * NK];   // [o][k], k contiguous (transposed from input)
    __shared__ float b1s[HID];
    __shared__ float snum[NK * 3];
    __shared__ float sden[NK];

    const int t = threadIdx.x;

    // stage weights
    for (int i = t; i < HID * NC / 4; i += 256)
        ((float4*)W1s)[i] = ((const float4*)W1)[i];
    for (int i = t; i < HID * NK; i += 256) {
        int o = i / NK, k = i % NK;
        W2s[i] = W2[k * HID + o];
    }
    if (t < HID)    b1s[t]  = b1[t];
    if (t < NK * 3) snum[t] = 0.0f;
    if (t < NK)     sden[t] = 0.0f;
    __syncthreads();

    const int g = blockIdx.x * 256 + t;   // grid is exact: NB*HW/256 blocks
    const int b = g / HW;
    const int p = g % HW;

    // load this pixel's feature vector into registers (coalesced per channel)
    const float* fptr = feat + (size_t)b * NC * HW + p;
    float f[NC];
#pragma unroll
    for (int c = 0; c < NC; c++) f[c] = __ldg(fptr + (size_t)c * HW);

    float logits[NK];
#pragma unroll
    for (int k = 0; k < NK; k++) logits[k] = 0.0f;

#pragma unroll 2
    for (int o = 0; o < HID; o++) {
        const float4* wv = (const float4*)(W1s + o * NC);
        float s0 = 0.f, s1 = 0.f, s2 = 0.f, s3 = 0.f;
#pragma unroll
        for (int q = 0; q < NC / 4; q++) {
            float4 w = wv[q];
            s0 = fmaf(f[4*q + 0], w.x, s0);
            s1 = fmaf(f[4*q + 1], w.y, s1);
            s2 = fmaf(f[4*q + 2], w.z, s2);
            s3 = fmaf(f[4*q + 3], w.w, s3);
        }
        float h = (s0 + s1) + (s2 + s3) + b1s[o];
        h = fmaxf(h, 0.0f);
        const float4* w2v = (const float4*)(W2s + o * NK);
#pragma unroll
        for (int q = 0; q < NK / 4; q++) {
            float4 w = w2v[q];
            logits[4*q + 0] = fmaf(h, w.x, logits[4*q + 0]);
            logits[4*q + 1] = fmaf(h, w.y, logits[4*q + 1]);
            logits[4*q + 2] = fmaf(h, w.z, logits[4*q + 2]);
            logits[4*q + 3] = fmaf(h, w.w, logits[4*q + 3]);
        }
    }

    // argmax (first-max tie-break, matches jnp.argmax) + softmax(SOFTEN * logits)
    float mx = logits[0];
    int   am = 0;
#pragma unroll
    for (int k = 1; k < NK; k++) {
        if (logits[k] > mx) { mx = logits[k]; am = k; }
    }
    float e[NK];
    float sum = 0.0f;
#pragma unroll
    for (int k = 0; k < NK; k++) {
        e[k] = __expf(SOFTEN * (logits[k] - mx));
        sum += e[k];
    }
    const float inv = 1.0f / sum;

    float* mo = out + OFF_M + (size_t)b * NK * HW + p;
#pragma unroll
    for (int k = 0; k < NK; k++) mo[(size_t)k * HW] = e[k] * inv;

    gArg[g] = (unsigned char)am;

    // block-level palette accumulation (all threads in block share same b: HW % 256 == 0)
    const float* ip = img + (size_t)b * 3 * HW + p;
    atomicAdd(&snum[am * 3 + 0], __ldg(ip));
    atomicAdd(&snum[am * 3 + 1], __ldg(ip + HW));
    atomicAdd(&snum[am * 3 + 2], __ldg(ip + 2 * HW));
    atomicAdd(&sden[am], 1.0f);
    __syncthreads();

    if (t < NK * 3) atomicAdd(&gNum[b * NK * 3 + t], snum[t]);
    if (t < NK)     atomicAdd(&gDen[b * NK + t], sden[t]);
}

__global__ void palette_kernel(float* __restrict__ out) {
    int t = threadIdx.x;   // one thread per (b,k)
    if (t < NB * NK) {
        float d = gDen[t] + EPSV;
#pragma unroll
        for (int c = 0; c < 3; c++) {
            float v = gNum[t * 3 + c] / d;
            gPal[t * 3 + c] = v;
            out[OFF_P + (size_t)t * 3 + c] = v;
        }
    }
}

__global__ __launch_bounds__(256) void transform_kernel(float* __restrict__ out) {
    __shared__ float pal[NB * NK * 3];
    int t = threadIdx.x;
    if (t < NB * NK * 3) pal[t] = gPal[t];
    __syncthreads();

    int g = blockIdx.x * 256 + t;
    int b = g / HW;
    int p = g % HW;
    int am = gArg[g];

    const float* pp = &pal[(b * NK + am) * 3];
    float* op = out + OFF_T + (size_t)b * 3 * HW + p;
    op[0]           = pp[0];
    op[(size_t)HW]     = pp[1];
    op[(size_t)2 * HW] = pp[2];
}

extern "C" void kernel_launch(void* const* d_in, const int* in_sizes, int n_in,
                              void* d_out, int out_size) {
    const float* img  = (const float*)d_in[0];
    const float* feat = (const float*)d_in[1];
    const float* W1   = (const float*)d_in[2];
    const float* b1   = (const float*)d_in[3];
    const float* W2   = (const float*)d_in[4];
    float* out = (float*)d_out;

    const int npix_blocks = NB * HW / 256;   // 4096

    zero_kernel<<<1, 256>>>();
    main_kernel<<<npix_blocks, 256>>>(img, feat, W1, b1, W2, out);
    palette_kernel<<<1, 64>>>(out);
    transform_kernel<<<npix_blocks, 256>>>(out);
}

// round 2
// speedup vs baseline: 1.1168x; 1.1168x over previous
#include <cuda_runtime.h>
#include <math.h>

#define HW     (512*512)
#define NB     4
#define NC     64
#define HID    128
#define NK     16
#define SOFTEN 10000.0f
#define EPSV   1e-8f

// out layout: transformed_img [4,3,512,512] | m [4,16,512,512] | palette [4,16,3,1,1]
#define OFF_T  ((size_t)0)
#define OFF_M  ((size_t)NB * 3 * HW)
#define OFF_P  (OFF_M + (size_t)NB * NK * HW)

// scratch (no allocations allowed)
__device__ float         gNum[NB * NK * 3];
__device__ float         gDen[NB * NK];
__device__ float         gPal[NB * NK * 3];
__device__ unsigned char gArg[NB * HW];

// ---- packed f32x2 helpers (sm_100+ only; ptxas never auto-emits FFMA2) ----
__device__ __forceinline__ unsigned long long pack2(float lo, float hi) {
    unsigned long long r;
    asm("mov.b64 %0, {%1, %2};" : "=l"(r) : "f"(lo), "f"(hi));
    return r;
}
__device__ __forceinline__ void unpack2(float& lo, float& hi, unsigned long long v) {
    asm("mov.b64 {%0, %1}, %2;" : "=f"(lo), "=f"(hi) : "l"(v));
}
#define FMA2(d, a, b, c) \
    asm("fma.rn.f32x2 %0, %1, %2, %3;" : "=l"(d) : "l"(a), "l"(b), "l"(c))
#define ADD2(d, a, b) \
    asm("add.rn.f32x2 %0, %1, %2;" : "=l"(d) : "l"(a), "l"(b))

__global__ void zero_kernel() {
    int t = threadIdx.x;
    if (t < NB * NK * 3) gNum[t] = 0.0f;
    if (t < NB * NK)     gDen[t] = 0.0f;
}

__global__ __launch_bounds__(256) void main_kernel(
    const float* __restrict__ img,
    const float* __restrict__ feat,
    const float* __restrict__ W1,
    const float* __restrict__ b1,
    const float* __restrict__ W2,
    float* __restrict__ out)
{
    __shared__ __align__(16) float W1s[HID * NC];   // [o][c], c contiguous
    __shared__ __align__(16) float W2s[HID * NK];   // [o][k], k contiguous
    __shared__ float b1s[HID];
    __shared__ float snum[NK * 3];
    __shared__ float sden[NK];

    const int t = threadIdx.x;

    // stage weights
    for (int i = t; i < HID * NC / 4; i += 256)
        ((float4*)W1s)[i] = ((const float4*)W1)[i];
    for (int i = t; i < HID * NK; i += 256) {
        int o = i / NK, k = i % NK;
        W2s[i] = W2[k * HID + o];
    }
    if (t < HID)    b1s[t]  = b1[t];
    if (t < NK * 3) snum[t] = 0.0f;
    if (t < NK)     sden[t] = 0.0f;
    __syncthreads();

    const int g = blockIdx.x * 256 + t;   // grid exact: NB*HW/256 blocks
    const int b = g / HW;
    const int p = g % HW;

    // load feature vector, pack channel pairs (c, c+1) into f32x2 regs
    const float* fptr = feat + (size_t)b * NC * HW + p;
    unsigned long long f2[NC / 2];
#pragma unroll
    for (int q = 0; q < NC / 2; q++) {
        float a = __ldg(fptr + (size_t)(2 * q)     * HW);
        float c = __ldg(fptr + (size_t)(2 * q + 1) * HW);
        f2[q] = pack2(a, c);
    }

    unsigned long long lp[NK / 2];        // logit pairs (2j, 2j+1)
#pragma unroll
    for (int j = 0; j < NK / 2; j++) lp[j] = 0ULL;

#pragma unroll 2
    for (int o = 0; o < HID; o++) {
        const ulonglong2* wv = (const ulonglong2*)(W1s + o * NC);  // 16 x (2 packs)
        unsigned long long a0 = 0ULL, a1 = 0ULL, a2 = 0ULL, a3 = 0ULL;
#pragma unroll
        for (int q = 0; q < NC / 8; q++) {     // 8 iters, 4 packs each
            ulonglong2 wA = wv[2 * q];
            ulonglong2 wB = wv[2 * q + 1];
            FMA2(a0, f2[4 * q + 0], wA.x, a0);
            FMA2(a1, f2[4 * q + 1], wA.y, a1);
            FMA2(a2, f2[4 * q + 2], wB.x, a2);
            FMA2(a3, f2[4 * q + 3], wB.y, a3);
        }
        unsigned long long s01, s23, s;
        ADD2(s01, a0, a1);
        ADD2(s23, a2, a3);
        ADD2(s, s01, s23);
        float slo, shi;
        unpack2(slo, shi, s);
        float h = fmaxf(slo + shi + b1s[o], 0.0f);

        unsigned long long hp = pack2(h, h);
        const ulonglong2* w2v = (const ulonglong2*)(W2s + o * NK); // 4 x (2 packs)
#pragma unroll
        for (int q = 0; q < NK / 4; q++) {
            ulonglong2 w = w2v[q];
            FMA2(lp[2 * q + 0], hp, w.x, lp[2 * q + 0]);
            FMA2(lp[2 * q + 1], hp, w.y, lp[2 * q + 1]);
        }
    }

    float logits[NK];
#pragma unroll
    for (int j = 0; j < NK / 2; j++)
        unpack2(logits[2 * j], logits[2 * j + 1], lp[j]);

    // argmax (first-max tie-break, matches jnp.argmax) + softmax(SOFTEN * logits)
    float mx = logits[0];
    int   am = 0;
#pragma unroll
    for (int k = 1; k < NK; k++) {
        if (logits[k] > mx) { mx = logits[k]; am = k; }
    }
    float e[NK];
    float sum = 0.0f;
#pragma unroll
    for (int k = 0; k < NK; k++) {
        e[k] = __expf(SOFTEN * (logits[k] - mx));
        sum += e[k];
    }
    const float inv = 1.0f / sum;

    float* mo = out + OFF_M + (size_t)b * NK * HW + p;
#pragma unroll
    for (int k = 0; k < NK; k++) mo[(size_t)k * HW] = e[k] * inv;

    gArg[g] = (unsigned char)am;

    // block-level palette accumulation (block's pixels share one b: HW % 256 == 0)
    const float* ip = img + (size_t)b * 3 * HW + p;
    atomicAdd(&snum[am * 3 + 0], __ldg(ip));
    atomicAdd(&snum[am * 3 + 1], __ldg(ip + HW));
    atomicAdd(&snum[am * 3 + 2], __ldg(ip + 2 * HW));
    atomicAdd(&sden[am], 1.0f);
    __syncthreads();

    if (t < NK * 3) atomicAdd(&gNum[b * NK * 3 + t], snum[t]);
    if (t < NK)     atomicAdd(&gDen[b * NK + t], sden[t]);
}

__global__ void palette_kernel(float* __restrict__ out) {
    int t = threadIdx.x;   // one thread per (b,k)
    if (t < NB * NK) {
        float d = gDen[t] + EPSV;
#pragma unroll
        for (int c = 0; c < 3; c++) {
            float v = gNum[t * 3 + c] / d;
            gPal[t * 3 + c] = v;
            out[OFF_P + (size_t)t * 3 + c] = v;
        }
    }
}

__global__ __launch_bounds__(256) void transform_kernel(float* __restrict__ out) {
    __shared__ float pal[NB * NK * 3];
    int t = threadIdx.x;
    if (t < NB * NK * 3) pal[t] = gPal[t];
    __syncthreads();

    int g = blockIdx.x * 256 + t;
    int b = g / HW;
    int p = g % HW;
    int am = gArg[g];

    const float* pp = &pal[(b * NK + am) * 3];
    float* op = out + OFF_T + (size_t)b * 3 * HW + p;
    op[0]              = pp[0];
    op[(size_t)HW]     = pp[1];
    op[(size_t)2 * HW] = pp[2];
}

extern "C" void kernel_launch(void* const* d_in, const int* in_sizes, int n_in,
                              void* d_out, int out_size) {
    const float* img  = (const float*)d_in[0];
    const float* feat = (const float*)d_in[1];
    const float* W1   = (const float*)d_in[2];
    const float* b1   = (const float*)d_in[3];
    const float* W2   = (const float*)d_in[4];
    float* out = (float*)d_out;

    const int npix_blocks = NB * HW / 256;   // 4096

    zero_kernel<<<1, 256>>>();
    main_kernel<<<npix_blocks, 256>>>(img, feat, W1, b1, W2, out);
    palette_kernel<<<1, 64>>>(out);
    transform_kernel<<<npix_blocks, 256>>>(out);
}